// round 15
// baseline (speedup 1.0000x reference)
#include <cuda.h>
#include <cuda_runtime.h>
#include <math.h>
#include <stdint.h>

#define BQ 4096
#define DD 256
#define NNEG 32768

#if (defined(__CUDA_ARCH_FEAT_SM103_ALL) || defined(__CUDA_ARCH_FEAT_SM100_ALL) || \
     (defined(__CUDA_ARCH_SPECIFIC__) && (__CUDA_ARCH_SPECIFIC__ == 1030 || __CUDA_ARCH_SPECIFIC__ == 1000)) || \
     (defined(__CUDA_ARCH_FAMILY_SPECIFIC__) && (__CUDA_ARCH_FAMILY_SPECIFIC__ == 1030 || __CUDA_ARCH_FAMILY_SPECIFIC__ == 1000)))
#define HAS_TCGEN05 1
#else
#define HAS_TCGEN05 0
#endif

// ---------------- scratch ----------------
__device__ float g_rowsum[BQ];
__device__ float g_colsum[BQ];
__device__ float g_negsum[BQ];
__device__ float g_diag[BQ];

__device__ __forceinline__ float get_inv_tau(const float* log_tau) {
    float t = expf(log_tau[0]);
    t = fminf(fmaxf(t, 1e-4f), 1.0f);
    return 1.0f / t;
}

// ---------------- generic PTX helpers ----------------
__device__ __forceinline__ uint32_t smem_u32(const void* p) {
    return (uint32_t)__cvta_generic_to_shared(p);
}
__device__ __forceinline__ void mbar_init(uint32_t a, uint32_t cnt) {
    asm volatile("mbarrier.init.shared.b64 [%0], %1;" :: "r"(a), "r"(cnt) : "memory");
}
__device__ __forceinline__ void mbar_wait(uint32_t a, uint32_t phase) {
    uint32_t done;
    do {
        asm volatile("{\n\t.reg .pred p;\n\t"
                     "mbarrier.try_wait.parity.shared::cta.b64 p, [%1], %2, 0x989680;\n\t"
                     "selp.b32 %0, 1, 0, p;\n\t}"
                     : "=r"(done) : "r"(a), "r"(phase) : "memory");
    } while (!done);
}
__device__ __forceinline__ void mbar_expect_tx(uint32_t a, uint32_t bytes) {
    asm volatile("mbarrier.arrive.expect_tx.shared.b64 _, [%0], %1;"
                 :: "r"(a), "r"(bytes) : "memory");
}
__device__ __forceinline__ void tma_load_2d(uint32_t dst, const CUtensorMap* map,
                                            int x, int y, uint32_t mbar) {
    asm volatile("cp.async.bulk.tensor.2d.shared::cta.global.tile.mbarrier::complete_tx::bytes "
                 "[%0], [%1, {%2, %3}], [%4];"
                 :: "r"(dst), "l"(map), "r"(x), "r"(y), "r"(mbar) : "memory");
}

#if HAS_TCGEN05
// ---------------- tcgen05 helpers (sm_103a only) ----------------
__device__ __forceinline__ void tc_alloc(uint32_t smem_dst, uint32_t ncols) {
    asm volatile("tcgen05.alloc.cta_group::1.sync.aligned.shared::cta.b32 [%0], %1;"
                 :: "r"(smem_dst), "r"(ncols) : "memory");
}
__device__ __forceinline__ void tc_relinquish() {
    asm volatile("tcgen05.relinquish_alloc_permit.cta_group::1.sync.aligned;");
}
__device__ __forceinline__ void tc_dealloc(uint32_t tmem, uint32_t ncols) {
    asm volatile("tcgen05.dealloc.cta_group::1.sync.aligned.b32 %0, %1;" :: "r"(tmem), "r"(ncols));
}
__device__ __forceinline__ void tc_commit(uint32_t mbar) {
    asm volatile("tcgen05.commit.cta_group::1.mbarrier::arrive::one.shared::cluster.b64 [%0];"
                 :: "r"(mbar) : "memory");
}
__device__ __forceinline__ void tc_fence_after() {
    asm volatile("tcgen05.fence::after_thread_sync;" ::: "memory");
}
__device__ __forceinline__ void tc_fence_before() {
    asm volatile("tcgen05.fence::before_thread_sync;" ::: "memory");
}
__device__ __forceinline__ void tc_wait_ld() {
    asm volatile("tcgen05.wait::ld.sync.aligned;" ::: "memory");
}
__device__ __forceinline__ void mma_tf32_ss(uint32_t d, uint64_t a, uint64_t b,
                                            uint32_t idesc, uint32_t en) {
    asm volatile("{\n\t.reg .pred p;\n\tsetp.ne.u32 p, %5, 0;\n\t"
                 "tcgen05.mma.cta_group::1.kind::tf32 [%0], %1, %2, %3, {%4,%4,%4,%4}, p;\n\t}"
                 :: "r"(d), "l"(a), "l"(b), "r"(idesc), "r"(0u), "r"(en) : "memory");
}
__device__ __forceinline__ void ldtm_x32(uint32_t* r, uint32_t tmem) {
    asm volatile(
        "tcgen05.ld.sync.aligned.32x32b.x32.b32 "
        "{%0, %1, %2, %3, %4, %5, %6, %7, "
        " %8, %9, %10, %11, %12, %13, %14, %15, "
        " %16, %17, %18, %19, %20, %21, %22, %23, "
        " %24, %25, %26, %27, %28, %29, %30, %31}, [%32];"
        : "=r"(r[0]), "=r"(r[1]), "=r"(r[2]), "=r"(r[3]),
          "=r"(r[4]), "=r"(r[5]), "=r"(r[6]), "=r"(r[7]),
          "=r"(r[8]), "=r"(r[9]), "=r"(r[10]), "=r"(r[11]),
          "=r"(r[12]), "=r"(r[13]), "=r"(r[14]), "=r"(r[15]),
          "=r"(r[16]), "=r"(r[17]), "=r"(r[18]), "=r"(r[19]),
          "=r"(r[20]), "=r"(r[21]), "=r"(r[22]), "=r"(r[23]),
          "=r"(r[24]), "=r"(r[25]), "=r"(r[26]), "=r"(r[27]),
          "=r"(r[28]), "=r"(r[29]), "=r"(r[30]), "=r"(r[31])
        : "r"(tmem));
}
// SMEM descriptor SW64: layout=4, version=1, SBO=32 (512B per 8-row group), LBO=1 (16B)
#define DESC_BASE_SW64 ((uint64_t(4) << 61) | (uint64_t(1) << 46) | (uint64_t(32) << 32) | (uint64_t(1) << 16))
__device__ __forceinline__ uint64_t make_desc64(uint32_t addr) {
    return DESC_BASE_SW64 | ((uint64_t)(addr >> 4) & 0x3FFF);
}
#endif // HAS_TCGEN05

// ---------------- tile config (R9/R12-proven; DO NOT TOUCH) ----------------
#define TM 128
#define TN 128
#define KC 16                    // 16 tf32 = 64B rows -> SW64
#define NCHUNK (DD / KC)         // 16
#define NSTAGE 4
#define DPRE 2                   // prefetch distance < NSTAGE (the R9 win)
#define STAGE_BYTES ((TM + TN) * KC * 4)   // 16384
#define NTILES ((BQ / TM) * (BQ / TN))     // 1024
// idesc: dtype=F32(1)@4, a/btype=TF32(2)@7/10, N/8@17, M/16@24
#define IDESC ((1u << 4) | (2u << 7) | (2u << 10) | ((TN / 8) << 17) | ((TM / 16) << 24))

// smem layout
#define SM_TMEM   0
#define SM_MBAR   64   // full[4]@+0..31, empty[4]@+32..63, done@+64
#define SM_ST0    1024
#define SM_A(s)   (SM_ST0 + (s) * STAGE_BYTES)
#define SM_B(s)   (SM_A(s) + TM * KC * 4)
#define EPAD      132
#define SM_TOTAL  (SM_ST0 + 128 * EPAD * 4)   // 68608 -> 3 CTAs/SM; E overlays stages

// ---------------------------------------------------------------- negatives + self-scan + zero
// 512 CTAs x 256 thr; warp-per-query. Batched dot phase (8 predicated rows, no
// shuffles) + deferred independent butterfly reductions -> high MLP.
__global__ void k_neg(const float* __restrict__ q, const float* __restrict__ n,
                      const int* __restrict__ counts, const float* __restrict__ log_tau,
                      float* __restrict__ out) {
    __shared__ int s_part[8];
    int tid = threadIdx.x;
    int w = tid >> 5, lane = tid & 31;
    int qb = blockIdx.x * 8;

    // zero accumulator slices (visible to gemm via stream order)
    if (tid < 8) {
        g_rowsum[qb + tid] = 0.f;
        g_colsum[qb + tid] = 0.f;
    }
    if (blockIdx.x == 0 && tid == 0) out[0] = 0.f;

    // base = sum counts[0..qb) : block-strided partial + block reduce
    int partial = 0;
    for (int t = tid; t < qb; t += 256) partial += counts[t];
    #pragma unroll
    for (int m = 16; m > 0; m >>= 1) partial += __shfl_xor_sync(0xFFFFFFFFu, partial, m);
    if (lane == 0) s_part[w] = partial;
    __syncthreads();
    int base = s_part[0] + s_part[1] + s_part[2] + s_part[3]
             + s_part[4] + s_part[5] + s_part[6] + s_part[7];

    // warp w -> query i = qb + w ; local prefix over counts[qb..qb+w)
    int i = qb + w;
    int loc = 0;
    for (int j = 0; j < w; j++) loc += counts[qb + j];   // L1-hit
    int off = base + loc;
    int cnt = counts[i];

    float inv_tau = get_inv_tau(log_tau);
    const float* qr = q + (size_t)i * DD;
    float4 b0 = ((const float4*)qr)[lane * 2 + 0];
    float4 b1 = ((const float4*)qr)[lane * 2 + 1];

    // ---- batch 1: rows 0..7 (predicated addresses; all loads issued up front) ----
    float d[16];
    #pragma unroll
    for (int j = 0; j < 8; j++) {
        int rj = (j < cnt) ? j : 0;                       // safe dup address (L1 hit)
        const float* nr = n + (size_t)(off + rj) * DD;
        float4 a0 = ((const float4*)nr)[lane * 2 + 0];
        float4 a1 = ((const float4*)nr)[lane * 2 + 1];
        d[j] = a0.x*b0.x + a0.y*b0.y + a0.z*b0.z + a0.w*b0.w
             + a1.x*b1.x + a1.y*b1.y + a1.z*b1.z + a1.w*b1.w;
    }
    // ---- batch 2: rows 8..15 (warp-uniform branch; cnt uniform per warp) ----
    if (cnt > 8) {
        #pragma unroll
        for (int j = 8; j < 16; j++) {
            int rj = (j < cnt) ? j : 0;
            const float* nr = n + (size_t)(off + rj) * DD;
            float4 a0 = ((const float4*)nr)[lane * 2 + 0];
            float4 a1 = ((const float4*)nr)[lane * 2 + 1];
            d[j] = a0.x*b0.x + a0.y*b0.y + a0.z*b0.z + a0.w*b0.w
                 + a1.x*b1.x + a1.y*b1.y + a1.z*b1.z + a1.w*b1.w;
        }
    } else {
        #pragma unroll
        for (int j = 8; j < 16; j++) d[j] = 0.f;
    }

    // ---- deferred reductions: independent butterfly chains, pipelined ----
    float part = 0.f;
    #pragma unroll
    for (int j = 0; j < 8; j++) {
        float v = d[j];
        v += __shfl_xor_sync(0xFFFFFFFFu, v, 16);
        v += __shfl_xor_sync(0xFFFFFFFFu, v, 8);
        v += __shfl_xor_sync(0xFFFFFFFFu, v, 4);
        v += __shfl_xor_sync(0xFFFFFFFFu, v, 2);
        v += __shfl_xor_sync(0xFFFFFFFFu, v, 1);
        if (j < cnt) part += __expf(v * inv_tau);
    }
    if (cnt > 8) {
        #pragma unroll
        for (int j = 8; j < 16; j++) {
            float v = d[j];
            v += __shfl_xor_sync(0xFFFFFFFFu, v, 16);
            v += __shfl_xor_sync(0xFFFFFFFFu, v, 8);
            v += __shfl_xor_sync(0xFFFFFFFFu, v, 4);
            v += __shfl_xor_sync(0xFFFFFFFFu, v, 2);
            v += __shfl_xor_sync(0xFFFFFFFFu, v, 1);
            if (j < cnt) part += __expf(v * inv_tau);
        }
    }
    if (lane == 0) g_negsum[i] = part;
}

// ---------------------------------------------------------------- GEMM + exp-sum epilogue
// EXACT R12 engine: warp 4 = TMA+MMA dispatcher, warps 0-3 = epilogue. 3 CTAs/SM.
__global__ __launch_bounds__(160, 3)
void k_gemm_tc(const __grid_constant__ CUtensorMap tma_a,
               const __grid_constant__ CUtensorMap tma_b,
               const float* __restrict__ q, const float* __restrict__ p,
               const float* __restrict__ log_tau) {
    int ti = blockIdx.x;
    int mi = ti & 31, ni = ti >> 5;
    int m0 = mi << 7, n0 = ni << 7;
#if HAS_TCGEN05
    extern __shared__ __align__(1024) char smem[];
    uint32_t sb = smem_u32(smem);
    int tid = threadIdx.x;
    int wid = tid >> 5;

    uint32_t mb_full[NSTAGE], mb_empty[NSTAGE];
    #pragma unroll
    for (int s = 0; s < NSTAGE; s++) {
        mb_full[s]  = sb + SM_MBAR + 8 * s;
        mb_empty[s] = sb + SM_MBAR + 32 + 8 * s;
    }
    uint32_t mb_done = sb + SM_MBAR + 64;

    if (wid == 4) { tc_alloc(sb + SM_TMEM, 128); tc_relinquish(); }
    if (tid == 0) {
        #pragma unroll
        for (int s = 0; s < NSTAGE; s++) { mbar_init(mb_full[s], 1); mbar_init(mb_empty[s], 1); }
        mbar_init(mb_done, 1);
    }
    __syncthreads();
    uint32_t tmem;
    asm volatile("ld.shared.b32 %0, [%1];" : "=r"(tmem) : "r"(sb + SM_TMEM));

    if (wid == 4) {
        if (tid == 128) {
            #pragma unroll
            for (int c = 0; c < DPRE; c++) {
                mbar_expect_tx(mb_full[c], STAGE_BYTES);
                tma_load_2d(sb + SM_A(c), &tma_a, c * KC, m0, mb_full[c]);
                tma_load_2d(sb + SM_B(c), &tma_b, c * KC, n0, mb_full[c]);
            }
            #pragma unroll 1
            for (int c = 0; c < NCHUNK; c++) {
                int pf = c + DPRE;      // refill AHEAD: stage consumed 2 iters ago
                if (pf < NCHUNK) {
                    int st = pf & 3;
                    if (pf >= NSTAGE)
                        mbar_wait(mb_empty[st], ((pf >> 2) - 1) & 1);
                    mbar_expect_tx(mb_full[st], STAGE_BYTES);
                    tma_load_2d(sb + SM_A(st), &tma_a, pf * KC, m0, mb_full[st]);
                    tma_load_2d(sb + SM_B(st), &tma_b, pf * KC, n0, mb_full[st]);
                }
                int s = c & 3;
                mbar_wait(mb_full[s], (c >> 2) & 1);
                uint64_t ad = make_desc64(sb + SM_A(s));
                uint64_t bd = make_desc64(sb + SM_B(s));
                mma_tf32_ss(tmem, ad,     bd,     IDESC, c > 0);  // K[0:8)
                mma_tf32_ss(tmem, ad + 2, bd + 2, IDESC, 1);      // K[8:16)
                tc_commit(mb_empty[s]);
            }
            tc_commit(mb_done);
        }
    } else {
        // epilogue warps (tid < 128; thread = row)
        mbar_wait(mb_done, 0);
        tc_fence_after();
        float inv_tau = get_inv_tau(log_tau);
        float* E = (float*)(smem + SM_ST0);
        float rowacc = 0.f;
        #pragma unroll
        for (int cc = 0; cc < 4; cc++) {
            uint32_t r[32];
            ldtm_x32(r, tmem + cc * 32);
            tc_wait_ld();
            #pragma unroll
            for (int j = 0; j < 32; j++) {
                float e = __expf(__uint_as_float(r[j]) * inv_tau);
                rowacc += e;
                E[(cc * 32 + j) * EPAD + tid] = e;   // E[col][row]
            }
        }
        atomicAdd(&g_rowsum[m0 + tid], rowacc);
        tc_fence_before();
    }
    __syncthreads();
    if (tid < 128) {
        float* E = (float*)(smem + SM_ST0);
        float csum = 0.f;
        const float4* Er = (const float4*)(E + tid * EPAD);
        #pragma unroll
        for (int k = 0; k < 32; k++) {
            float4 v = Er[k];
            csum += v.x + v.y + v.z + v.w;
        }
        atomicAdd(&g_colsum[n0 + tid], csum);
        if (m0 == n0)
            g_diag[m0 + tid] = logf(E[tid * EPAD + tid]);
    }
    __syncthreads();
    if (wid == 4) tc_dealloc(tmem, 128);

#else  // fallback (non-sm_103a passes; never runs on GB300)
    int tid = threadIdx.x;
    float inv_tau = get_inv_tau(log_tau);
    if (tid < 128) {
        int m = m0 + tid;
        const float* qr = q + (size_t)m * DD;
        float rowacc = 0.f;
        for (int nn = 0; nn < TN; nn++) {
            const float* pr = p + (size_t)(n0 + nn) * DD;
            float dot = 0.f;
            for (int k = 0; k < DD; k++) dot += qr[k] * pr[k];
            float lg = dot * inv_tau;
            if (m == n0 + nn) g_diag[m] = lg;
            float e = __expf(lg);
            rowacc += e;
            atomicAdd(&g_colsum[n0 + nn], e);
        }
        atomicAdd(&g_rowsum[m], rowacc);
    }
#endif
}

// ---------------------------------------------------------------- finalize (32 blocks x 128, warp reduce)
__global__ void k_final(float* __restrict__ out) {
    int tid = threadIdx.x;
    int lane = tid & 31;
    int i = blockIdx.x * 128 + tid;
    float a = 2.f * g_diag[i]
            - logf(g_rowsum[i] + g_negsum[i])
            - logf(g_colsum[i]);
    #pragma unroll
    for (int m = 16; m > 0; m >>= 1) a += __shfl_xor_sync(0xFFFFFFFFu, a, m);
    if (lane == 0) atomicAdd(out, -a / (2.f * (float)BQ));
}

// ---------------------------------------------------------------- launch
typedef CUresult (*pfn_encode_t)(CUtensorMap*, CUtensorMapDataType, cuuint32_t, void*,
                                 const cuuint64_t*, const cuuint64_t*, const cuuint32_t*,
                                 const cuuint32_t*, CUtensorMapInterleave, CUtensorMapSwizzle,
                                 CUtensorMapL2promotion, CUtensorMapFloatOOBfill);

extern "C" void kernel_launch(void* const* d_in, const int* in_sizes, int n_in,
                              void* d_out, int out_size) {
    const float* q       = (const float*)d_in[0];
    const float* p       = (const float*)d_in[1];
    const float* n       = (const float*)d_in[2];
    const int*   counts  = (const int*)d_in[3];
    const float* log_tau = (const float*)d_in[4];
    float* out = (float*)d_out;

    static pfn_encode_t s_encode = nullptr;
    static bool attr_set = false;
    if (!attr_set) {
        cudaFuncSetAttribute(k_gemm_tc, cudaFuncAttributeMaxDynamicSharedMemorySize, SM_TOTAL);
        cudaFuncSetAttribute(k_gemm_tc, cudaFuncAttributePreferredSharedMemoryCarveout, 100);
        cudaDriverEntryPointQueryResult qres;
        cudaGetDriverEntryPoint("cuTensorMapEncodeTiled", (void**)&s_encode,
                                cudaEnableDefault, &qres);
        attr_set = true;
    }

    CUtensorMap ta, tb;
    cuuint64_t gdim[2]    = { DD, BQ };
    cuuint64_t gstride[1] = { DD * sizeof(float) };
    cuuint32_t box[2]     = { KC, TM };
    cuuint32_t estr[2]    = { 1, 1 };
    s_encode(&ta, CU_TENSOR_MAP_DATA_TYPE_FLOAT32, 2, (void*)q, gdim, gstride, box, estr,
             CU_TENSOR_MAP_INTERLEAVE_NONE, CU_TENSOR_MAP_SWIZZLE_64B,
             CU_TENSOR_MAP_L2_PROMOTION_L2_128B, CU_TENSOR_MAP_FLOAT_OOB_FILL_NONE);
    s_encode(&tb, CU_TENSOR_MAP_DATA_TYPE_FLOAT32, 2, (void*)p, gdim, gstride, box, estr,
             CU_TENSOR_MAP_INTERLEAVE_NONE, CU_TENSOR_MAP_SWIZZLE_64B,
             CU_TENSOR_MAP_L2_PROMOTION_L2_128B, CU_TENSOR_MAP_FLOAT_OOB_FILL_NONE);

    k_neg<<<BQ / 8, 256>>>(q, n, counts, log_tau, out);
    k_gemm_tc<<<NTILES, 160, SM_TOTAL>>>(ta, tb, q, p, log_tau);
    k_final<<<32, 128>>>(out);
}

// round 16
// speedup vs baseline: 1.0054x; 1.0054x over previous
#include <cuda.h>
#include <cuda_runtime.h>
#include <math.h>
#include <stdint.h>

#define BQ 4096
#define DD 256
#define NNEG 32768

#if (defined(__CUDA_ARCH_FEAT_SM103_ALL) || defined(__CUDA_ARCH_FEAT_SM100_ALL) || \
     (defined(__CUDA_ARCH_SPECIFIC__) && (__CUDA_ARCH_SPECIFIC__ == 1030 || __CUDA_ARCH_SPECIFIC__ == 1000)) || \
     (defined(__CUDA_ARCH_FAMILY_SPECIFIC__) && (__CUDA_ARCH_FAMILY_SPECIFIC__ == 1030 || __CUDA_ARCH_FAMILY_SPECIFIC__ == 1000)))
#define HAS_TCGEN05 1
#else
#define HAS_TCGEN05 0
#endif

// ---------------- scratch ----------------
// g_rowsum / g_colsum: zero at module load; k_final resets them after reading,
// so every graph replay starts from zero (no separate zeroing launch).
__device__ float g_rowsum[BQ];
__device__ float g_colsum[BQ];
__device__ float g_negsum[BQ];
__device__ float g_diag[BQ];

__device__ __forceinline__ float get_inv_tau(const float* log_tau) {
    float t = expf(log_tau[0]);
    t = fminf(fmaxf(t, 1e-4f), 1.0f);
    return 1.0f / t;
}

// ---------------- generic PTX helpers ----------------
__device__ __forceinline__ uint32_t smem_u32(const void* p) {
    return (uint32_t)__cvta_generic_to_shared(p);
}
__device__ __forceinline__ void mbar_init(uint32_t a, uint32_t cnt) {
    asm volatile("mbarrier.init.shared.b64 [%0], %1;" :: "r"(a), "r"(cnt) : "memory");
}
__device__ __forceinline__ void mbar_wait(uint32_t a, uint32_t phase) {
    uint32_t done;
    do {
        asm volatile("{\n\t.reg .pred p;\n\t"
                     "mbarrier.try_wait.parity.shared::cta.b64 p, [%1], %2, 0x989680;\n\t"
                     "selp.b32 %0, 1, 0, p;\n\t}"
                     : "=r"(done) : "r"(a), "r"(phase) : "memory");
    } while (!done);
}
__device__ __forceinline__ void mbar_expect_tx(uint32_t a, uint32_t bytes) {
    asm volatile("mbarrier.arrive.expect_tx.shared.b64 _, [%0], %1;"
                 :: "r"(a), "r"(bytes) : "memory");
}
__device__ __forceinline__ void tma_load_2d(uint32_t dst, const CUtensorMap* map,
                                            int x, int y, uint32_t mbar) {
    asm volatile("cp.async.bulk.tensor.2d.shared::cta.global.tile.mbarrier::complete_tx::bytes "
                 "[%0], [%1, {%2, %3}], [%4];"
                 :: "r"(dst), "l"(map), "r"(x), "r"(y), "r"(mbar) : "memory");
}
__device__ __forceinline__ void bar_sync_128() {   // named barrier 1, warps 0-3 only
    asm volatile("bar.sync 1, 128;" ::: "memory");
}

#if HAS_TCGEN05
// ---------------- tcgen05 helpers (sm_103a only) ----------------
__device__ __forceinline__ void tc_alloc(uint32_t smem_dst, uint32_t ncols) {
    asm volatile("tcgen05.alloc.cta_group::1.sync.aligned.shared::cta.b32 [%0], %1;"
                 :: "r"(smem_dst), "r"(ncols) : "memory");
}
__device__ __forceinline__ void tc_relinquish() {
    asm volatile("tcgen05.relinquish_alloc_permit.cta_group::1.sync.aligned;");
}
__device__ __forceinline__ void tc_dealloc(uint32_t tmem, uint32_t ncols) {
    asm volatile("tcgen05.dealloc.cta_group::1.sync.aligned.b32 %0, %1;" :: "r"(tmem), "r"(ncols));
}
__device__ __forceinline__ void tc_commit(uint32_t mbar) {
    asm volatile("tcgen05.commit.cta_group::1.mbarrier::arrive::one.shared::cluster.b64 [%0];"
                 :: "r"(mbar) : "memory");
}
__device__ __forceinline__ void tc_fence_after() {
    asm volatile("tcgen05.fence::after_thread_sync;" ::: "memory");
}
__device__ __forceinline__ void tc_fence_before() {
    asm volatile("tcgen05.fence::before_thread_sync;" ::: "memory");
}
__device__ __forceinline__ void tc_wait_ld() {
    asm volatile("tcgen05.wait::ld.sync.aligned;" ::: "memory");
}
__device__ __forceinline__ void mma_tf32_ss(uint32_t d, uint64_t a, uint64_t b,
                                            uint32_t idesc, uint32_t en) {
    asm volatile("{\n\t.reg .pred p;\n\tsetp.ne.u32 p, %5, 0;\n\t"
                 "tcgen05.mma.cta_group::1.kind::tf32 [%0], %1, %2, %3, {%4,%4,%4,%4}, p;\n\t}"
                 :: "r"(d), "l"(a), "l"(b), "r"(idesc), "r"(0u), "r"(en) : "memory");
}
__device__ __forceinline__ void ldtm_x32(uint32_t* r, uint32_t tmem) {
    asm volatile(
        "tcgen05.ld.sync.aligned.32x32b.x32.b32 "
        "{%0, %1, %2, %3, %4, %5, %6, %7, "
        " %8, %9, %10, %11, %12, %13, %14, %15, "
        " %16, %17, %18, %19, %20, %21, %22, %23, "
        " %24, %25, %26, %27, %28, %29, %30, %31}, [%32];"
        : "=r"(r[0]), "=r"(r[1]), "=r"(r[2]), "=r"(r[3]),
          "=r"(r[4]), "=r"(r[5]), "=r"(r[6]), "=r"(r[7]),
          "=r"(r[8]), "=r"(r[9]), "=r"(r[10]), "=r"(r[11]),
          "=r"(r[12]), "=r"(r[13]), "=r"(r[14]), "=r"(r[15]),
          "=r"(r[16]), "=r"(r[17]), "=r"(r[18]), "=r"(r[19]),
          "=r"(r[20]), "=r"(r[21]), "=r"(r[22]), "=r"(r[23]),
          "=r"(r[24]), "=r"(r[25]), "=r"(r[26]), "=r"(r[27]),
          "=r"(r[28]), "=r"(r[29]), "=r"(r[30]), "=r"(r[31])
        : "r"(tmem));
}
// SMEM descriptor SW64: layout=4, version=1, SBO=32 (512B per 8-row group), LBO=1 (16B)
#define DESC_BASE_SW64 ((uint64_t(4) << 61) | (uint64_t(1) << 46) | (uint64_t(32) << 32) | (uint64_t(1) << 16))
__device__ __forceinline__ uint64_t make_desc64(uint32_t addr) {
    return DESC_BASE_SW64 | ((uint64_t)(addr >> 4) & 0x3FFF);
}
#endif // HAS_TCGEN05

// ---------------- tile config (R9/R12-proven; DO NOT TOUCH) ----------------
#define TM 128
#define TN 128
#define KC 16                    // 16 tf32 = 64B rows -> SW64
#define NCHUNK (DD / KC)         // 16
#define NSTAGE 4
#define DPRE 2                   // prefetch distance < NSTAGE (the R9 win)
#define STAGE_BYTES ((TM + TN) * KC * 4)   // 16384
#define NTILES ((BQ / TM) * (BQ / TN))     // 1024
// idesc: dtype=F32(1)@4, a/btype=TF32(2)@7/10, N/8@17, M/16@24
#define IDESC ((1u << 4) | (2u << 7) | (2u << 10) | ((TN / 8) << 17) | ((TM / 16) << 24))

// smem layout
#define SM_TMEM   0
#define SM_MBAR   64    // full[4]@+0..31, empty[4]@+32..63, done@+64
#define SM_NPART  144   // 4 ints: per-warp count partials (outside stage area)
#define SM_ST0    1024
#define SM_A(s)   (SM_ST0 + (s) * STAGE_BYTES)
#define SM_B(s)   (SM_A(s) + TM * KC * 4)
#define EPAD      132
#define SM_TOTAL  (SM_ST0 + 128 * EPAD * 4)   // 68608 -> 3 CTAs/SM; E overlays stages

// ---------------------------------------------------------------- GEMM + negatives + exp-sum epilogue
// R12 tile engine; warps 0-3 additionally compute 4 queries' negative exp-sums
// (query 4*ti + w) DURING the mainloop, overlapping the dispatcher's TMA+MMA.
__global__ __launch_bounds__(160, 3)
void k_gemm_tc(const __grid_constant__ CUtensorMap tma_a,
               const __grid_constant__ CUtensorMap tma_b,
               const float* __restrict__ q, const float* __restrict__ p,
               const float* __restrict__ nemb, const int* __restrict__ counts,
               const float* __restrict__ log_tau, float* __restrict__ out) {
    int ti = blockIdx.x;
    int mi = ti & 31, ni = ti >> 5;
    int m0 = mi << 7, n0 = ni << 7;
    int tid = threadIdx.x;
#if HAS_TCGEN05
    extern __shared__ __align__(1024) char smem[];
    uint32_t sb = smem_u32(smem);
    int wid = tid >> 5, lane = tid & 31;

    if (ti == 0 && tid == 0) out[0] = 0.f;   // out poisoned by harness; k_final atomicAdds

    uint32_t mb_full[NSTAGE], mb_empty[NSTAGE];
    #pragma unroll
    for (int s = 0; s < NSTAGE; s++) {
        mb_full[s]  = sb + SM_MBAR + 8 * s;
        mb_empty[s] = sb + SM_MBAR + 32 + 8 * s;
    }
    uint32_t mb_done = sb + SM_MBAR + 64;

    if (wid == 4) { tc_alloc(sb + SM_TMEM, 128); tc_relinquish(); }
    if (tid == 0) {
        #pragma unroll
        for (int s = 0; s < NSTAGE; s++) { mbar_init(mb_full[s], 1); mbar_init(mb_empty[s], 1); }
        mbar_init(mb_done, 1);
    }
    __syncthreads();
    uint32_t tmem;
    asm volatile("ld.shared.b32 %0, [%1];" : "=r"(tmem) : "r"(sb + SM_TMEM));

    if (wid == 4) {
        if (tid == 128) {
            #pragma unroll
            for (int c = 0; c < DPRE; c++) {
                mbar_expect_tx(mb_full[c], STAGE_BYTES);
                tma_load_2d(sb + SM_A(c), &tma_a, c * KC, m0, mb_full[c]);
                tma_load_2d(sb + SM_B(c), &tma_b, c * KC, n0, mb_full[c]);
            }
            #pragma unroll 1
            for (int c = 0; c < NCHUNK; c++) {
                int pf = c + DPRE;      // refill AHEAD: stage consumed 2 iters ago
                if (pf < NCHUNK) {
                    int st = pf & 3;
                    if (pf >= NSTAGE)
                        mbar_wait(mb_empty[st], ((pf >> 2) - 1) & 1);
                    mbar_expect_tx(mb_full[st], STAGE_BYTES);
                    tma_load_2d(sb + SM_A(st), &tma_a, pf * KC, m0, mb_full[st]);
                    tma_load_2d(sb + SM_B(st), &tma_b, pf * KC, n0, mb_full[st]);
                }
                int s = c & 3;
                mbar_wait(mb_full[s], (c >> 2) & 1);
                uint64_t ad = make_desc64(sb + SM_A(s));
                uint64_t bd = make_desc64(sb + SM_B(s));
                mma_tf32_ss(tmem, ad,     bd,     IDESC, c > 0);  // K[0:8)
                mma_tf32_ss(tmem, ad + 2, bd + 2, IDESC, 1);      // K[8:16)
                tc_commit(mb_empty[s]);
            }
            tc_commit(mb_done);
        }
    } else {
        // ============ warps 0-3: negatives for queries 4*ti + w (overlaps mainloop) ============
        float inv_tau = get_inv_tau(log_tau);
        {
            int qb4 = ti << 2;
            int i = qb4 + wid;
            int* s_part = (int*)(smem + SM_NPART);
            // base = sum counts[0..qb4): 128-thread strided partial + warp butterflies
            int partial = 0;
            for (int t = tid; t < qb4; t += 128) partial += counts[t];
            #pragma unroll
            for (int m = 16; m > 0; m >>= 1) partial += __shfl_xor_sync(0xFFFFFFFFu, partial, m);
            if (lane == 0) s_part[wid] = partial;
            bar_sync_128();
            int base = s_part[0] + s_part[1] + s_part[2] + s_part[3];
            int loc = 0;
            #pragma unroll
            for (int j = 0; j < 3; j++) if (j < wid) loc += counts[qb4 + j];
            int off = base + loc;
            int cnt = counts[i];

            const float* qr = q + (size_t)i * DD;
            float4 b0 = ((const float4*)qr)[lane * 2 + 0];
            float4 b1 = ((const float4*)qr)[lane * 2 + 1];

            float d[16];
            #pragma unroll
            for (int j = 0; j < 8; j++) {
                int rj = (j < cnt) ? j : 0;
                const float* nr = nemb + (size_t)(off + rj) * DD;
                float4 a0 = ((const float4*)nr)[lane * 2 + 0];
                float4 a1 = ((const float4*)nr)[lane * 2 + 1];
                d[j] = a0.x*b0.x + a0.y*b0.y + a0.z*b0.z + a0.w*b0.w
                     + a1.x*b1.x + a1.y*b1.y + a1.z*b1.z + a1.w*b1.w;
            }
            if (cnt > 8) {
                #pragma unroll
                for (int j = 8; j < 16; j++) {
                    int rj = (j < cnt) ? j : 0;
                    const float* nr = nemb + (size_t)(off + rj) * DD;
                    float4 a0 = ((const float4*)nr)[lane * 2 + 0];
                    float4 a1 = ((const float4*)nr)[lane * 2 + 1];
                    d[j] = a0.x*b0.x + a0.y*b0.y + a0.z*b0.z + a0.w*b0.w
                         + a1.x*b1.x + a1.y*b1.y + a1.z*b1.z + a1.w*b1.w;
                }
            } else {
                #pragma unroll
                for (int j = 8; j < 16; j++) d[j] = 0.f;
            }
            float part = 0.f;
            #pragma unroll
            for (int j = 0; j < 8; j++) {
                float v = d[j];
                v += __shfl_xor_sync(0xFFFFFFFFu, v, 16);
                v += __shfl_xor_sync(0xFFFFFFFFu, v, 8);
                v += __shfl_xor_sync(0xFFFFFFFFu, v, 4);
                v += __shfl_xor_sync(0xFFFFFFFFu, v, 2);
                v += __shfl_xor_sync(0xFFFFFFFFu, v, 1);
                if (j < cnt) part += __expf(v * inv_tau);
            }
            if (cnt > 8) {
                #pragma unroll
                for (int j = 8; j < 16; j++) {
                    float v = d[j];
                    v += __shfl_xor_sync(0xFFFFFFFFu, v, 16);
                    v += __shfl_xor_sync(0xFFFFFFFFu, v, 8);
                    v += __shfl_xor_sync(0xFFFFFFFFu, v, 4);
                    v += __shfl_xor_sync(0xFFFFFFFFu, v, 2);
                    v += __shfl_xor_sync(0xFFFFFFFFu, v, 1);
                    if (j < cnt) part += __expf(v * inv_tau);
                }
            }
            if (lane == 0) g_negsum[i] = part;
        }
        // ============ epilogue (unchanged R12) ============
        mbar_wait(mb_done, 0);
        tc_fence_after();
        float* E = (float*)(smem + SM_ST0);
        float rowacc = 0.f;
        #pragma unroll
        for (int cc = 0; cc < 4; cc++) {
            uint32_t r[32];
            ldtm_x32(r, tmem + cc * 32);
            tc_wait_ld();
            #pragma unroll
            for (int j = 0; j < 32; j++) {
                float e = __expf(__uint_as_float(r[j]) * inv_tau);
                rowacc += e;
                E[(cc * 32 + j) * EPAD + tid] = e;   // E[col][row]
            }
        }
        atomicAdd(&g_rowsum[m0 + tid], rowacc);
        tc_fence_before();
    }
    __syncthreads();
    if (tid < 128) {
        float* E = (float*)(smem + SM_ST0);
        float csum = 0.f;
        const float4* Er = (const float4*)(E + tid * EPAD);
        #pragma unroll
        for (int k = 0; k < 32; k++) {
            float4 v = Er[k];
            csum += v.x + v.y + v.z + v.w;
        }
        atomicAdd(&g_colsum[n0 + tid], csum);
        if (m0 == n0)
            g_diag[m0 + tid] = logf(E[tid * EPAD + tid]);
    }
    __syncthreads();
    if (wid == 4) tc_dealloc(tmem, 128);

#else  // fallback (non-sm_103a passes; never runs on GB300)
    float inv_tau = get_inv_tau(log_tau);
    if (ti == 0 && tid == 0) out[0] = 0.f;
    if (tid < 128) {
        int m = m0 + tid;
        const float* qr = q + (size_t)m * DD;
        float rowacc = 0.f;
        for (int nn = 0; nn < TN; nn++) {
            const float* pr = p + (size_t)(n0 + nn) * DD;
            float dot = 0.f;
            for (int k = 0; k < DD; k++) dot += qr[k] * pr[k];
            float lg = dot * inv_tau;
            if (m == n0 + nn) g_diag[m] = lg;
            float e = __expf(lg);
            rowacc += e;
            atomicAdd(&g_colsum[n0 + nn], e);
        }
        atomicAdd(&g_rowsum[m], rowacc);
    }
    // negatives: threads 128..131 handle query 4*ti + (tid-128) serially
    if (tid >= 128 && tid < 132) {
        int i = (ti << 2) + (tid - 128);
        int off = 0;
        for (int j = 0; j < i; j++) off += counts[j];
        int cnt = counts[i];
        const float* qr = q + (size_t)i * DD;
        float part = 0.f;
        for (int k = 0; k < cnt; k++) {
            const float* nr = nemb + (size_t)(off + k) * DD;
            float dot = 0.f;
            for (int kk = 0; kk < DD; kk++) dot += qr[kk] * nr[kk];
            part += __expf(dot * inv_tau);
        }
        g_negsum[i] = part;
    }
#endif
}

// ---------------------------------------------------------------- finalize (32 blocks x 128, warp reduce)
// Self-cleaning: resets g_rowsum/g_colsum after reading so the next graph
// replay starts from zero without a dedicated zeroing launch.
__global__ void k_final(float* __restrict__ out) {
    int tid = threadIdx.x;
    int lane = tid & 31;
    int i = blockIdx.x * 128 + tid;
    float rs = g_rowsum[i], cs = g_colsum[i];
    float a = 2.f * g_diag[i]
            - logf(rs + g_negsum[i])
            - logf(cs);
    g_rowsum[i] = 0.f;
    g_colsum[i] = 0.f;
    #pragma unroll
    for (int m = 16; m > 0; m >>= 1) a += __shfl_xor_sync(0xFFFFFFFFu, a, m);
    if (lane == 0) atomicAdd(out, -a / (2.f * (float)BQ));
}

// ---------------------------------------------------------------- launch
typedef CUresult (*pfn_encode_t)(CUtensorMap*, CUtensorMapDataType, cuuint32_t, void*,
                                 const cuuint64_t*, const cuuint64_t*, const cuuint32_t*,
                                 const cuuint32_t*, CUtensorMapInterleave, CUtensorMapSwizzle,
                                 CUtensorMapL2promotion, CUtensorMapFloatOOBfill);

extern "C" void kernel_launch(void* const* d_in, const int* in_sizes, int n_in,
                              void* d_out, int out_size) {
    const float* q       = (const float*)d_in[0];
    const float* p       = (const float*)d_in[1];
    const float* n       = (const float*)d_in[2];
    const int*   counts  = (const int*)d_in[3];
    const float* log_tau = (const float*)d_in[4];
    float* out = (float*)d_out;

    static pfn_encode_t s_encode = nullptr;
    static bool attr_set = false;
    if (!attr_set) {
        cudaFuncSetAttribute(k_gemm_tc, cudaFuncAttributeMaxDynamicSharedMemorySize, SM_TOTAL);
        cudaFuncSetAttribute(k_gemm_tc, cudaFuncAttributePreferredSharedMemoryCarveout, 100);
        cudaDriverEntryPointQueryResult qres;
        cudaGetDriverEntryPoint("cuTensorMapEncodeTiled", (void**)&s_encode,
                                cudaEnableDefault, &qres);
        attr_set = true;
    }

    CUtensorMap ta, tb;
    cuuint64_t gdim[2]    = { DD, BQ };
    cuuint64_t gstride[1] = { DD * sizeof(float) };
    cuuint32_t box[2]     = { KC, TM };
    cuuint32_t estr[2]    = { 1, 1 };
    s_encode(&ta, CU_TENSOR_MAP_DATA_TYPE_FLOAT32, 2, (void*)q, gdim, gstride, box, estr,
             CU_TENSOR_MAP_INTERLEAVE_NONE, CU_TENSOR_MAP_SWIZZLE_64B,
             CU_TENSOR_MAP_L2_PROMOTION_L2_128B, CU_TENSOR_MAP_FLOAT_OOB_FILL_NONE);
    s_encode(&tb, CU_TENSOR_MAP_DATA_TYPE_FLOAT32, 2, (void*)p, gdim, gstride, box, estr,
             CU_TENSOR_MAP_INTERLEAVE_NONE, CU_TENSOR_MAP_SWIZZLE_64B,
             CU_TENSOR_MAP_L2_PROMOTION_L2_128B, CU_TENSOR_MAP_FLOAT_OOB_FILL_NONE);

    k_gemm_tc<<<NTILES, 160, SM_TOTAL>>>(ta, tb, q, p, n, counts, log_tau, out);
    k_final<<<32, 128>>>(out);
}